// round 14
// baseline (speedup 1.0000x reference)
#include <cuda_runtime.h>
#include <cuda_bf16.h>
#include <cuda_fp16.h>
#include <cstdint>
#include <math.h>

// Block: B=1, T=4096, C=1024, H=16, hs=64
#define SEQ 4096
#define EMB 1024
#define NHEAD 16
#define HS 64
#define C3 3072
#define CFC 4096

// ---------------- device scratch (no allocations allowed) ----------------
__device__ __half g_h[SEQ * EMB];          // LN out (fp16)
__device__ __half g_qh[SEQ * EMB];         // Q fp16 [seq][emb]
__device__ __half g_kh[NHEAD * SEQ * HS];  // K fp16 [hd][seq][64]
__device__ __half g_vt[NHEAD * HS * SEQ];  // V fp16 transposed [hd][d][seq]
__device__ __half g_attn[SEQ * EMB];       // attention out (fp16)
__device__ float g_x1[SEQ * EMB];          // x + attn_proj
__device__ __half g_fc[SEQ * CFC];         // gelu(fc) (fp16)
// transposed fp16 weights: Wt[n][k]
__device__ __half g_wqkv[C3 * EMB];
__device__ __half g_wproj[EMB * EMB];
__device__ __half g_wfc[CFC * EMB];
__device__ __half g_wmlp[EMB * CFC];

__device__ __forceinline__ float gelu_exact(float v) {
    return 0.5f * v * (1.0f + erff(v * 0.70710678118654752440f));
}

// ---- smem/cp.async/mma helpers ----
__device__ __forceinline__ uint32_t smem_u32(const void* p) {
    uint32_t a;
    asm("{ .reg .u64 t; cvta.to.shared.u64 t, %1; cvt.u32.u64 %0, t; }" : "=r"(a) : "l"(p));
    return a;
}
__device__ __forceinline__ void cp16(void* sp, const void* gp) {
    asm volatile("cp.async.cg.shared.global [%0], [%1], 16;" :: "r"(smem_u32(sp)), "l"(gp));
}
__device__ __forceinline__ void cp_commit() {
    asm volatile("cp.async.commit_group;" ::: "memory");
}
__device__ __forceinline__ void cp_wait0() {
    asm volatile("cp.async.wait_group 0;" ::: "memory");
}
__device__ __forceinline__ void cp_wait1() {
    asm volatile("cp.async.wait_group 1;" ::: "memory");
}
__device__ __forceinline__ void ldsm4(uint32_t* r, uint32_t addr) {
    asm volatile("ldmatrix.sync.aligned.m8n8.x4.shared.b16 {%0,%1,%2,%3}, [%4];"
                 : "=r"(r[0]), "=r"(r[1]), "=r"(r[2]), "=r"(r[3]) : "r"(addr));
}
__device__ __forceinline__ void mma16816(float* c, const uint32_t* a, uint32_t b0, uint32_t b1) {
    asm volatile(
        "mma.sync.aligned.m16n8k16.row.col.f32.f16.f16.f32 "
        "{%0,%1,%2,%3}, {%4,%5,%6,%7}, {%8,%9}, {%0,%1,%2,%3};"
        : "+f"(c[0]), "+f"(c[1]), "+f"(c[2]), "+f"(c[3])
        : "r"(a[0]), "r"(a[1]), "r"(a[2]), "r"(a[3]), "r"(b0), "r"(b1));
}
__device__ __forceinline__ uint32_t pack_h2(float x, float y) {
    __half2 h = __floats2half2_rn(x, y);
    return *reinterpret_cast<uint32_t*>(&h);
}

// ---------------- LayerNorm -> fp16 ----------------
__global__ void ln_kernel(const float* __restrict__ x, const float* __restrict__ w,
                          __half* __restrict__ outp) {
    const int row = blockIdx.x;
    const int tid = threadIdx.x;  // 256, 4 floats each
    const float4 v = reinterpret_cast<const float4*>(x + (size_t)row * EMB)[tid];

    float s = v.x + v.y + v.z + v.w;
    float q = v.x * v.x + v.y * v.y + v.z * v.z + v.w * v.w;
    #pragma unroll
    for (int off = 16; off > 0; off >>= 1) {
        s += __shfl_xor_sync(0xffffffffu, s, off);
        q += __shfl_xor_sync(0xffffffffu, q, off);
    }
    __shared__ float ws[8], wq[8], s_mean, s_rstd;
    const int wid = tid >> 5, lane = tid & 31;
    if (lane == 0) { ws[wid] = s; wq[wid] = q; }
    __syncthreads();
    if (tid == 0) {
        float S = 0.f, Q = 0.f;
        #pragma unroll
        for (int i = 0; i < 8; i++) { S += ws[i]; Q += wq[i]; }
        float mean = S * (1.0f / EMB);
        float var = Q * (1.0f / EMB) - mean * mean;
        s_mean = mean;
        s_rstd = rsqrtf(var + 1e-5f);
    }
    __syncthreads();
    const float mean = s_mean, rstd = s_rstd;
    const float4 g = reinterpret_cast<const float4*>(w)[tid];
    __half2 o0 = __floats2half2_rn((v.x - mean) * rstd * g.x, (v.y - mean) * rstd * g.y);
    __half2 o1 = __floats2half2_rn((v.z - mean) * rstd * g.z, (v.w - mean) * rstd * g.w);
    *reinterpret_cast<__half2*>(outp + (size_t)row * EMB + tid * 4) = o0;
    *reinterpret_cast<__half2*>(outp + (size_t)row * EMB + tid * 4 + 2) = o1;
}

// ---------------- weight transpose: W[K,N] fp32 -> Wt[N,K] fp16 ----------------
__global__ __launch_bounds__(256) void wt_kernel(const float* __restrict__ W,
                                                 __half* __restrict__ tw,
                                                 int K, int N) {
    __shared__ float tile[32][33];
    const int bn = blockIdx.x * 32;
    const int bk = blockIdx.y * 32;
    const int tx = threadIdx.x & 31, ty = threadIdx.x >> 5;
    #pragma unroll
    for (int r = ty; r < 32; r += 8)
        tile[r][tx] = W[(size_t)(bk + r) * N + bn + tx];
    __syncthreads();
    #pragma unroll
    for (int r = ty; r < 32; r += 8)
        tw[(size_t)(bn + r) * K + bk + tx] = __float2half(tile[tx][r]);
}

// ---------------- raw-MMA GEMM: single-pass fp16, KC=64, 2-stage cp.async ----------------
// 128x128 CTA (4 warps, 64x64 warp tile).
// EPI: 1 = C = R + acc (fp32), 2 = gelu(acc)->fp16 Ch, 3 = qkv split (Q/K/Vt layouts)
#define KC2 64
#define SPAD 72                         // conflict-free ldmatrix (144B row stride)
#define SLAB (128 * SPAD)
#define STAGE_ELEMS (2 * SLAB)          // A, B
#define VPAD 136

template <int EPI>
__global__ __launch_bounds__(128, 2) void mma_gemm(
    const __half* __restrict__ A, const __half* __restrict__ Bf,
    const float* __restrict__ R, float* __restrict__ C,
    __half* __restrict__ Ch, __half* __restrict__ Kh, __half* __restrict__ Vt,
    int M, int N, int K) {
    extern __shared__ char smraw[];
    __half* sm = reinterpret_cast<__half*>(smraw);
    const uint32_t smb = smem_u32(sm);

    const int tid = threadIdx.x;
    const int warp = tid >> 5, lane = tid & 31;
    const int wm = warp & 1;        // 2 warps in M (64 rows)
    const int wn = warp >> 1;       // 2 warps in N (64 cols)
    const int gid = lane >> 2, tig = lane & 3;
    const int bm = blockIdx.y * 128, bn = blockIdx.x * 128;

    float acc[4][8][4];
    if (EPI == 1) {
        #pragma unroll
        for (int mt = 0; mt < 4; mt++) {
            const size_t r0 = (size_t)(bm + wm * 64 + mt * 16 + gid) * N;
            const size_t r1 = r0 + 8 * N;
            #pragma unroll
            for (int nt = 0; nt < 8; nt++) {
                const int col = bn + wn * 64 + nt * 8 + tig * 2;
                const float2 v0 = *reinterpret_cast<const float2*>(R + r0 + col);
                const float2 v1 = *reinterpret_cast<const float2*>(R + r1 + col);
                acc[mt][nt][0] = v0.x; acc[mt][nt][1] = v0.y;
                acc[mt][nt][2] = v1.x; acc[mt][nt][3] = v1.y;
            }
        }
    } else {
        #pragma unroll
        for (int mt = 0; mt < 4; mt++)
            #pragma unroll
            for (int nt = 0; nt < 8; nt++)
                #pragma unroll
                for (int t = 0; t < 4; t++) acc[mt][nt][t] = 0.f;
    }

    const int NC = K / KC2;

    // stage loader: 2 slabs x 128 rows x 64 cols (8 cp16/row-slab) -> 16 cp16/thread
    auto load_stage = [&](int buf, int k0) {
        __half* st = sm + buf * STAGE_ELEMS;
        #pragma unroll
        for (int o = 0; o < 8; o++) {
            const int idx = tid + o * 128;       // 0..1023
            const int row = idx >> 3, seg = idx & 7;
            const int soff = row * SPAD + seg * 8;
            cp16(st + soff,        A + (size_t)(bm + row) * K + k0 + seg * 8);
            cp16(st + SLAB + soff, Bf + (size_t)(bn + row) * K + k0 + seg * 8);
        }
    };

    const int a_row = wm * 64 + (lane & 15);
    const int a_col = (lane >> 4) << 3;
    const int b_row = wn * 64 + (lane & 7) + ((lane >> 4) << 3);
    const int b_col = ((lane >> 3) & 1) << 3;

    load_stage(0, 0);
    cp_commit();

    for (int c = 0; c < NC; c++) {
        if (c + 1 < NC) {
            load_stage((c + 1) & 1, (c + 1) * KC2);
            cp_commit();
            cp_wait1();
        } else {
            cp_wait0();
        }
        __syncthreads();

        const uint32_t st = smb + (c & 1) * STAGE_ELEMS * 2;  // bytes
        const uint32_t sA = st;
        const uint32_t sB = st + SLAB * 2;

        #pragma unroll
        for (int kk = 0; kk < KC2 / 16; kk++) {
            uint32_t bh[8][2];
            #pragma unroll
            for (int p = 0; p < 4; p++) {
                const uint32_t boff = ((b_row + p * 16) * SPAD + kk * 16 + b_col) * 2;
                uint32_t t4[4];
                ldsm4(t4, sB + boff);
                bh[2 * p][0] = t4[0]; bh[2 * p][1] = t4[1];
                bh[2 * p + 1][0] = t4[2]; bh[2 * p + 1][1] = t4[3];
            }
            #pragma unroll
            for (int mt = 0; mt < 4; mt++) {
                const uint32_t aoff = ((a_row + mt * 16) * SPAD + kk * 16 + a_col) * 2;
                uint32_t ah[4];
                ldsm4(ah, sA + aoff);
                #pragma unroll
                for (int nt = 0; nt < 8; nt++)
                    mma16816(acc[mt][nt], ah, bh[nt][0], bh[nt][1]);
            }
        }
        __syncthreads();
    }

    // ---- epilogue ----
    if (EPI == 1) {
        #pragma unroll
        for (int mt = 0; mt < 4; mt++) {
            const size_t r0 = (size_t)(bm + wm * 64 + mt * 16 + gid) * N;
            const size_t r1 = r0 + 8 * N;
            #pragma unroll
            for (int nt = 0; nt < 8; nt++) {
                const int col = bn + wn * 64 + nt * 8 + tig * 2;
                *reinterpret_cast<float2*>(C + r0 + col) =
                    make_float2(acc[mt][nt][0], acc[mt][nt][1]);
                *reinterpret_cast<float2*>(C + r1 + col) =
                    make_float2(acc[mt][nt][2], acc[mt][nt][3]);
            }
        }
    } else if (EPI == 2) {
        #pragma unroll
        for (int mt = 0; mt < 4; mt++) {
            const size_t r0 = (size_t)(bm + wm * 64 + mt * 16 + gid) * N;
            const size_t r1 = r0 + 8 * N;
            #pragma unroll
            for (int nt = 0; nt < 8; nt++) {
                const int col = bn + wn * 64 + nt * 8 + tig * 2;
                *reinterpret_cast<__half2*>(&Ch[r0 + col]) =
                    __floats2half2_rn(gelu_exact(acc[mt][nt][0]), gelu_exact(acc[mt][nt][1]));
                *reinterpret_cast<__half2*>(&Ch[r1 + col]) =
                    __floats2half2_rn(gelu_exact(acc[mt][nt][2]), gelu_exact(acc[mt][nt][3]));
            }
        }
    } else {
        // EPI == 3: qkv split.
        const int region = bn >> 10;    // 0 = q, 1 = k, 2 = v
        if (region == 0) {
            #pragma unroll
            for (int mt = 0; mt < 4; mt++) {
                const size_t r0 = (size_t)(bm + wm * 64 + mt * 16 + gid) * EMB;
                const size_t r1 = r0 + 8 * EMB;
                #pragma unroll
                for (int nt = 0; nt < 8; nt++) {
                    const int col = bn + wn * 64 + nt * 8 + tig * 2;
                    *reinterpret_cast<__half2*>(&Ch[r0 + col]) =
                        __floats2half2_rn(acc[mt][nt][0], acc[mt][nt][1]);
                    *reinterpret_cast<__half2*>(&Ch[r1 + col]) =
                        __floats2half2_rn(acc[mt][nt][2], acc[mt][nt][3]);
                }
            }
        } else if (region == 1) {
            const int hd = ((bn - 1024) >> 6) + wn;
            #pragma unroll
            for (int mt = 0; mt < 4; mt++) {
                const int row = bm + wm * 64 + mt * 16 + gid;
                const size_t k0 = ((size_t)hd * SEQ + row) * HS;
                const size_t k1 = k0 + 8 * HS;
                #pragma unroll
                for (int nt = 0; nt < 8; nt++) {
                    const int cc = nt * 8 + tig * 2;
                    *reinterpret_cast<__half2*>(&Kh[k0 + cc]) =
                        __floats2half2_rn(acc[mt][nt][0], acc[mt][nt][1]);
                    *reinterpret_cast<__half2*>(&Kh[k1 + cc]) =
                        __floats2half2_rn(acc[mt][nt][2], acc[mt][nt][3]);
                }
            }
        } else {
            __half* vs = sm;   // 128 x VPAD fp16 (34.8 KB)
            #pragma unroll
            for (int mt = 0; mt < 4; mt++) {
                const int lr0 = wm * 64 + mt * 16 + gid;
                #pragma unroll
                for (int nt = 0; nt < 8; nt++) {
                    const int lc = wn * 64 + nt * 8 + tig * 2;
                    *reinterpret_cast<__half2*>(&vs[lr0 * VPAD + lc]) =
                        __floats2half2_rn(acc[mt][nt][0], acc[mt][nt][1]);
                    *reinterpret_cast<__half2*>(&vs[(lr0 + 8) * VPAD + lc]) =
                        __floats2half2_rn(acc[mt][nt][2], acc[mt][nt][3]);
                }
            }
            __syncthreads();
            const int hdb = (bn - 2048) >> 6;
            #pragma unroll
            for (int i = 0; i < 64; i++) {
                const int idx = tid + i * 128;   // 0..8191
                const int d = idx >> 6;          // 0..127
                const int rp = idx & 63;         // row pair
                const __half2 v2 = __halves2half2(vs[(2 * rp) * VPAD + d],
                                                  vs[(2 * rp + 1) * VPAD + d]);
                const int hd = hdb + (d >> 6), dd = d & 63;
                *reinterpret_cast<__half2*>(
                    &Vt[((size_t)hd * HS + dd) * SEQ + bm + 2 * rp]) = v2;
            }
        }
    }
}

// ---------------- FA2 flash attention: 128-row q tiles, 8 warps ----------------
#define KVPAD 72
#define KVTILE (64 * KVPAD)
#define QTILE (128 * KVPAD)

__global__ __launch_bounds__(256) void flash2(
    const __half* __restrict__ qh,
    const __half* __restrict__ kh, const __half* __restrict__ vt,
    __half* __restrict__ outp) {
    extern __shared__ char smraw[];
    __half* Qs = reinterpret_cast<__half*>(smraw);   // 128 x 72
    __half* KB = Qs + QTILE;                         // [2 buf][Kh,Vt][64 x 72]

    const int tid = threadIdx.x;
    const int warp = tid >> 5, lane = tid & 31;
    const int gid = lane >> 2, tig = lane & 3;
    const int qb = (int)gridDim.x - 1 - (int)blockIdx.x;   // heavy tiles first
    const int qm = qb * 128;
    const int hd = blockIdx.y;

    {
        const __half2 sc = __floats2half2_rn(0.125f, 0.125f);  // exact (power of 2)
        for (int i = tid; i < 4096; i += 256) {
            const int r = i >> 5, c2 = (i & 31) * 2;
            const __half2 q2 = *reinterpret_cast<const __half2*>(
                qh + (size_t)(qm + r) * EMB + hd * HS + c2);
            *reinterpret_cast<__half2*>(&Qs[r * KVPAD + c2]) = __hmul2(q2, sc);
        }
    }
    __syncthreads();

    uint32_t qa[4][4];
    const int row0 = warp * 16 + gid;
    #pragma unroll
    for (int kk = 0; kk < 4; kk++) {
        qa[kk][0] = *reinterpret_cast<const uint32_t*>(&Qs[row0 * KVPAD + kk * 16 + tig * 2]);
        qa[kk][1] = *reinterpret_cast<const uint32_t*>(&Qs[(row0 + 8) * KVPAD + kk * 16 + tig * 2]);
        qa[kk][2] = *reinterpret_cast<const uint32_t*>(&Qs[row0 * KVPAD + kk * 16 + 8 + tig * 2]);
        qa[kk][3] = *reinterpret_cast<const uint32_t*>(&Qs[(row0 + 8) * KVPAD + kk * 16 + 8 + tig * 2]);
    }

    float o[8][4];
    #pragma unroll
    for (int j = 0; j < 8; j++)
        #pragma unroll
        for (int t = 0; t < 4; t++) o[j][t] = 0.f;
    float m0 = -1e30f, m1 = -1e30f, l0 = 0.f, l1 = 0.f;

    const size_t khb = (size_t)hd * SEQ * HS;
    const size_t vtb = (size_t)hd * HS * SEQ;
    const int NKT = 2 * qb + 2;

    auto prefetch = [&](int bufi, int kt) {
        __half* st = KB + bufi * (2 * KVTILE);
        #pragma unroll
        for (int o2 = 0; o2 < 2; o2++) {
            const int idx = tid + o2 * 256;   // 0..511
            const int r = idx >> 3, seg = idx & 7;
            const int so = r * KVPAD + seg * 8;
            cp16(st + so,          kh + khb + (size_t)(kt * 64 + r) * HS + seg * 8);
            cp16(st + KVTILE + so, vt + vtb + (size_t)r * SEQ + kt * 64 + seg * 8);
        }
    };

    prefetch(0, 0);
    cp_commit();

    for (int kt = 0; kt < NKT; kt++) {
        if (kt + 1 < NKT) {
            prefetch((kt + 1) & 1, kt + 1);
            cp_commit();
            cp_wait1();
        } else {
            cp_wait0();
        }
        __syncthreads();

        __half* st = KB + (kt & 1) * (2 * KVTILE);
        const __half* Kh = st;
        const __half* Vt = st + KVTILE;

        float s[8][4];
        #pragma unroll
        for (int j = 0; j < 8; j++)
            #pragma unroll
            for (int t = 0; t < 4; t++) s[j][t] = 0.f;
        #pragma unroll
        for (int kk = 0; kk < 4; kk++)
            #pragma unroll
            for (int j = 0; j < 8; j++) {
                const int off = (j * 8 + gid) * KVPAD + kk * 16 + tig * 2;
                const uint32_t b0 = *reinterpret_cast<const uint32_t*>(&Kh[off]);
                const uint32_t b1 = *reinterpret_cast<const uint32_t*>(&Kh[off + 8]);
                mma16816(s[j], qa[kk], b0, b1);
            }

        if (kt * 64 + 63 > qm + warp * 16) {
            const int rg0 = qm + row0;
            const int rg1 = rg0 + 8;
            #pragma unroll
            for (int j = 0; j < 8; j++) {
                const int c0 = kt * 64 + j * 8 + tig * 2;
                if (c0 > rg0)         s[j][0] = -1e30f;
                if (c0 + 1 > rg0)     s[j][1] = -1e30f;
                if (c0 > rg1)         s[j][2] = -1e30f;
                if (c0 + 1 > rg1)     s[j][3] = -1e30f;
            }
        }

        float mx0 = -1e30f, mx1 = -1e30f;
        #pragma unroll
        for (int j = 0; j < 8; j++) {
            mx0 = fmaxf(mx0, fmaxf(s[j][0], s[j][1]));
            mx1 = fmaxf(mx1, fmaxf(s[j][2], s[j][3]));
        }
        mx0 = fmaxf(mx0, __shfl_xor_sync(0xffffffffu, mx0, 1));
        mx0 = fmaxf(mx0, __shfl_xor_sync(0xffffffffu, mx0, 2));
        mx1 = fmaxf(mx1, __shfl_xor_sync(0xffffffffu, mx1, 1));
        mx1 = fmaxf(mx1, __shfl_xor_sync(0xffffffffu, mx1, 2));
        const float mn0 = fmaxf(m0, mx0), mn1 = fmaxf(m1, mx1);
        const float al0 = __expf(m0 - mn0), al1 = __expf(m1 - mn1);
        float rs0 = 0.f, rs1 = 0.f;
        #pragma unroll
        for (int j = 0; j < 8; j++) {
            s[j][0] = __expf(s[j][0] - mn0);
            s[j][1] = __expf(s[j][1] - mn0);
            s[j][2] = __expf(s[j][2] - mn1);
            s[j][3] = __expf(s[j][3] - mn1);
            rs0 += s[j][0] + s[j][1];
            rs1 += s[j][2] + s[j][3];
        }
        rs0 += __shfl_xor_sync(0xffffffffu, rs0, 1);
        rs0 += __shfl_xor_sync(0xffffffffu, rs0, 2);
        rs1 += __shfl_xor_sync(0xffffffffu, rs1, 1);
        rs1 += __shfl_xor_sync(0xffffffffu, rs1, 2);
        l0 = l0 * al0 + rs0;
        l1 = l1 * al1 + rs1;
        m0 = mn0;
        m1 = mn1;
        #pragma unroll
        for (int j = 0; j < 8; j++) {
            o[j][0] *= al0; o[j][1] *= al0;
            o[j][2] *= al1; o[j][3] *= al1;
        }

        #pragma unroll
        for (int kk = 0; kk < 4; kk++) {
            uint32_t pa[4];
            pa[0] = pack_h2(s[2 * kk][0], s[2 * kk][1]);
            pa[1] = pack_h2(s[2 * kk][2], s[2 * kk][3]);
            pa[2] = pack_h2(s[2 * kk + 1][0], s[2 * kk + 1][1]);
            pa[3] = pack_h2(s[2 * kk + 1][2], s[2 * kk + 1][3]);
            #pragma unroll
            for (int j = 0; j < 8; j++) {
                const int off = (j * 8 + gid) * KVPAD + kk * 16 + tig * 2;
                const uint32_t b0 = *reinterpret_cast<const uint32_t*>(&Vt[off]);
                const uint32_t b1 = *reinterpret_cast<const uint32_t*>(&Vt[off + 8]);
                mma16816(o[j], pa, b0, b1);
            }
        }
        __syncthreads();
    }

    const float inv0 = 1.0f / l0, inv1 = 1.0f / l1;
    #pragma unroll
    for (int j = 0; j < 8; j++) {
        const int d = hd * HS + j * 8 + tig * 2;
        const size_t r0o = (size_t)(qm + row0) * EMB + d;
        const size_t r1o = (size_t)(qm + row0 + 8) * EMB + d;
        *reinterpret_cast<__half2*>(&outp[r0o]) =
            __floats2half2_rn(o[j][0] * inv0, o[j][1] * inv0);
        *reinterpret_cast<__half2*>(&outp[r1o]) =
            __floats2half2_rn(o[j][2] * inv1, o[j][3] * inv1);
    }
}

// ---------------- launch ----------------
extern "C" void kernel_launch(void* const* d_in, const int* in_sizes, int n_in,
                              void* d_out, int out_size) {
    const float* x           = (const float*)d_in[0];
    const float* w_qkv       = (const float*)d_in[1];
    const float* w_attn_proj = (const float*)d_in[2];
    const float* w_fc        = (const float*)d_in[3];
    const float* w_mlp_proj  = (const float*)d_in[4];
    const float* ln1_w       = (const float*)d_in[5];
    const float* ln2_w       = (const float*)d_in[6];
    float* out = (float*)d_out;

    __half *p_h, *p_attn, *p_fc, *p_qh, *p_kh, *p_vt;
    __half *p_wqkv, *p_wproj, *p_wfc, *p_wmlp;
    float *p_x1;
    cudaGetSymbolAddress((void**)&p_h, g_h);
    cudaGetSymbolAddress((void**)&p_qh, g_qh);
    cudaGetSymbolAddress((void**)&p_kh, g_kh);
    cudaGetSymbolAddress((void**)&p_vt, g_vt);
    cudaGetSymbolAddress((void**)&p_attn, g_attn);
    cudaGetSymbolAddress((void**)&p_x1, g_x1);
    cudaGetSymbolAddress((void**)&p_fc, g_fc);
    cudaGetSymbolAddress((void**)&p_wqkv, g_wqkv);
    cudaGetSymbolAddress((void**)&p_wproj, g_wproj);
    cudaGetSymbolAddress((void**)&p_wfc, g_wfc);
    cudaGetSymbolAddress((void**)&p_wmlp, g_wmlp);

    const int gemm_smem = 2 * STAGE_ELEMS * (int)sizeof(__half);        // 73,728 B
    cudaFuncSetAttribute(mma_gemm<1>, cudaFuncAttributeMaxDynamicSharedMemorySize, gemm_smem);
    cudaFuncSetAttribute(mma_gemm<2>, cudaFuncAttributeMaxDynamicSharedMemorySize, gemm_smem);
    cudaFuncSetAttribute(mma_gemm<3>, cudaFuncAttributeMaxDynamicSharedMemorySize, gemm_smem);
    const int flash_smem = (QTILE + 4 * KVTILE) * (int)sizeof(__half);  // 55,296 B
    cudaFuncSetAttribute(flash2, cudaFuncAttributeMaxDynamicSharedMemorySize, flash_smem);

    // 0. h = LN(x, ln1)
    ln_kernel<<<SEQ, 256>>>(x, ln1_w, p_h);
    // 1-4. weight transpose to fp16
    wt_kernel<<<dim3(C3 / 32, EMB / 32), 256>>>(w_qkv, p_wqkv, EMB, C3);
    wt_kernel<<<dim3(EMB / 32, EMB / 32), 256>>>(w_attn_proj, p_wproj, EMB, EMB);
    wt_kernel<<<dim3(CFC / 32, EMB / 32), 256>>>(w_fc, p_wfc, EMB, CFC);
    wt_kernel<<<dim3(EMB / 32, CFC / 32), 256>>>(w_mlp_proj, p_wmlp, CFC, EMB);
    // 5. qkv = h @ w_qkv -> Q fp16 / K [hd][s][64] / V transposed (fused layouts)
    mma_gemm<3><<<dim3(C3 / 128, SEQ / 128), 128, gemm_smem>>>(
        p_h, p_wqkv, nullptr, nullptr, p_qh, p_kh, p_vt, SEQ, C3, EMB);
    // 6. attention (FA2, 128-row q tiles)
    flash2<<<dim3(SEQ / 128, NHEAD), 256, flash_smem>>>(p_qh, p_kh, p_vt, p_attn);
    // 7. x1 = x + attn @ w_attn_proj
    mma_gemm<1><<<dim3(EMB / 128, SEQ / 128), 128, gemm_smem>>>(
        p_attn, p_wproj, x, p_x1, nullptr, nullptr, nullptr, SEQ, EMB, EMB);
    // 8. h = LN(x1, ln2)
    ln_kernel<<<SEQ, 256>>>(p_x1, ln2_w, p_h);
    // 9. fc = gelu(h @ w_fc)
    mma_gemm<2><<<dim3(CFC / 128, SEQ / 128), 128, gemm_smem>>>(
        p_h, p_wfc, nullptr, nullptr, p_fc, nullptr, nullptr, SEQ, CFC, EMB);
    // 10. out = x1 + fc @ w_mlp_proj
    mma_gemm<1><<<dim3(EMB / 128, SEQ / 128), 128, gemm_smem>>>(
        p_fc, p_wmlp, p_x1, out, nullptr, nullptr, nullptr, SEQ, EMB, CFC);
}

// round 15
// speedup vs baseline: 1.0486x; 1.0486x over previous
#include <cuda_runtime.h>
#include <cuda_bf16.h>
#include <cuda_fp16.h>
#include <cstdint>
#include <math.h>

// Block: B=1, T=4096, C=1024, H=16, hs=64
#define SEQ 4096
#define EMB 1024
#define NHEAD 16
#define HS 64
#define C3 3072
#define CFC 4096

// ---------------- device scratch (no allocations allowed) ----------------
__device__ __half g_h[SEQ * EMB];          // LN out (fp16)
__device__ __half g_qh[SEQ * EMB];         // Q fp16 [seq][emb]
__device__ __half g_kh[NHEAD * SEQ * HS];  // K fp16 [hd][seq][64]
__device__ __half g_vt[NHEAD * HS * SEQ];  // V fp16 transposed [hd][d][seq]
__device__ __half g_attn[SEQ * EMB];       // attention out (fp16)
__device__ float g_x1[SEQ * EMB];          // x + attn_proj
__device__ __half g_fc[SEQ * CFC];         // gelu(fc) (fp16)
// transposed fp16 weights: Wt[n][k]
__device__ __half g_wqkv[C3 * EMB];
__device__ __half g_wproj[EMB * EMB];
__device__ __half g_wfc[CFC * EMB];
__device__ __half g_wmlp[EMB * CFC];

__device__ __forceinline__ float gelu_exact(float v) {
    return 0.5f * v * (1.0f + erff(v * 0.70710678118654752440f));
}

// ---- smem/cp.async/mma helpers ----
__device__ __forceinline__ uint32_t smem_u32(const void* p) {
    uint32_t a;
    asm("{ .reg .u64 t; cvta.to.shared.u64 t, %1; cvt.u32.u64 %0, t; }" : "=r"(a) : "l"(p));
    return a;
}
__device__ __forceinline__ void cp16(void* sp, const void* gp) {
    asm volatile("cp.async.cg.shared.global [%0], [%1], 16;" :: "r"(smem_u32(sp)), "l"(gp));
}
__device__ __forceinline__ void cp_commit() {
    asm volatile("cp.async.commit_group;" ::: "memory");
}
__device__ __forceinline__ void cp_wait0() {
    asm volatile("cp.async.wait_group 0;" ::: "memory");
}
__device__ __forceinline__ void cp_wait1() {
    asm volatile("cp.async.wait_group 1;" ::: "memory");
}
__device__ __forceinline__ void cp_wait2() {
    asm volatile("cp.async.wait_group 2;" ::: "memory");
}
__device__ __forceinline__ void ldsm4(uint32_t* r, uint32_t addr) {
    asm volatile("ldmatrix.sync.aligned.m8n8.x4.shared.b16 {%0,%1,%2,%3}, [%4];"
                 : "=r"(r[0]), "=r"(r[1]), "=r"(r[2]), "=r"(r[3]) : "r"(addr));
}
__device__ __forceinline__ void mma16816(float* c, const uint32_t* a, uint32_t b0, uint32_t b1) {
    asm volatile(
        "mma.sync.aligned.m16n8k16.row.col.f32.f16.f16.f32 "
        "{%0,%1,%2,%3}, {%4,%5,%6,%7}, {%8,%9}, {%0,%1,%2,%3};"
        : "+f"(c[0]), "+f"(c[1]), "+f"(c[2]), "+f"(c[3])
        : "r"(a[0]), "r"(a[1]), "r"(a[2]), "r"(a[3]), "r"(b0), "r"(b1));
}
__device__ __forceinline__ uint32_t pack_h2(float x, float y) {
    __half2 h = __floats2half2_rn(x, y);
    return *reinterpret_cast<uint32_t*>(&h);
}

// ---------------- LayerNorm -> fp16 ----------------
__global__ void ln_kernel(const float* __restrict__ x, const float* __restrict__ w,
                          __half* __restrict__ outp) {
    const int row = blockIdx.x;
    const int tid = threadIdx.x;  // 256, 4 floats each
    const float4 v = reinterpret_cast<const float4*>(x + (size_t)row * EMB)[tid];

    float s = v.x + v.y + v.z + v.w;
    float q = v.x * v.x + v.y * v.y + v.z * v.z + v.w * v.w;
    #pragma unroll
    for (int off = 16; off > 0; off >>= 1) {
        s += __shfl_xor_sync(0xffffffffu, s, off);
        q += __shfl_xor_sync(0xffffffffu, q, off);
    }
    __shared__ float ws[8], wq[8], s_mean, s_rstd;
    const int wid = tid >> 5, lane = tid & 31;
    if (lane == 0) { ws[wid] = s; wq[wid] = q; }
    __syncthreads();
    if (tid == 0) {
        float S = 0.f, Q = 0.f;
        #pragma unroll
        for (int i = 0; i < 8; i++) { S += ws[i]; Q += wq[i]; }
        float mean = S * (1.0f / EMB);
        float var = Q * (1.0f / EMB) - mean * mean;
        s_mean = mean;
        s_rstd = rsqrtf(var + 1e-5f);
    }
    __syncthreads();
    const float mean = s_mean, rstd = s_rstd;
    const float4 g = reinterpret_cast<const float4*>(w)[tid];
    __half2 o0 = __floats2half2_rn((v.x - mean) * rstd * g.x, (v.y - mean) * rstd * g.y);
    __half2 o1 = __floats2half2_rn((v.z - mean) * rstd * g.z, (v.w - mean) * rstd * g.w);
    *reinterpret_cast<__half2*>(outp + (size_t)row * EMB + tid * 4) = o0;
    *reinterpret_cast<__half2*>(outp + (size_t)row * EMB + tid * 4 + 2) = o1;
}

// ---------------- weight transpose: W[K,N] fp32 -> Wt[N,K] fp16, 64x64 tiles ----------------
__global__ __launch_bounds__(256) void wt_kernel(const float* __restrict__ W,
                                                 __half* __restrict__ tw,
                                                 int K, int N) {
    __shared__ float tile[64][65];
    const int bn = blockIdx.x * 64;
    const int bk = blockIdx.y * 64;
    const int r0 = threadIdx.x >> 4;            // 0..15
    const int c4 = (threadIdx.x & 15) * 4;      // 0..60
    #pragma unroll
    for (int rr = 0; rr < 4; rr++) {
        const int row = r0 + rr * 16;
        const float4 v = *reinterpret_cast<const float4*>(
            W + (size_t)(bk + row) * N + bn + c4);
        tile[row][c4 + 0] = v.x;
        tile[row][c4 + 1] = v.y;
        tile[row][c4 + 2] = v.z;
        tile[row][c4 + 3] = v.w;
    }
    __syncthreads();
    #pragma unroll
    for (int i = 0; i < 8; i++) {
        const int idx = threadIdx.x + i * 256;   // 0..2047
        const int orow = idx >> 5;               // 0..63 (n)
        const int ocp = idx & 31;                // half2 pair 0..31 (k/2)
        const __half2 h2 = __floats2half2_rn(tile[2 * ocp][orow], tile[2 * ocp + 1][orow]);
        *reinterpret_cast<__half2*>(&tw[(size_t)(bn + orow) * K + bk + 2 * ocp]) = h2;
    }
}

// ---------------- raw-MMA GEMM: single-pass fp16, KC=32, 3-stage cp.async (R13) ----------------
// 128x128 CTA (4 warps, 64x64 warp tile).
// EPI: 1 = C = R + acc (fp32), 2 = gelu(acc)->fp16 Ch, 3 = qkv split (Q/K/Vt layouts)
#define KC2 32
#define SPAD 40                         // conflict-free ldmatrix (80B row stride)
#define SLAB (128 * SPAD)
#define STAGE_ELEMS (2 * SLAB)          // A, B
#define VPAD 136

template <int EPI>
__global__ __launch_bounds__(128, 2) void mma_gemm(
    const __half* __restrict__ A, const __half* __restrict__ Bf,
    const float* __restrict__ R, float* __restrict__ C,
    __half* __restrict__ Ch, __half* __restrict__ Kh, __half* __restrict__ Vt,
    int M, int N, int K) {
    extern __shared__ char smraw[];
    __half* sm = reinterpret_cast<__half*>(smraw);
    const uint32_t smb = smem_u32(sm);

    const int tid = threadIdx.x;
    const int warp = tid >> 5, lane = tid & 31;
    const int wm = warp & 1;        // 2 warps in M (64 rows)
    const int wn = warp >> 1;       // 2 warps in N (64 cols)
    const int gid = lane >> 2, tig = lane & 3;
    const int bm = blockIdx.y * 128, bn = blockIdx.x * 128;

    float acc[4][8][4];
    if (EPI == 1) {
        #pragma unroll
        for (int mt = 0; mt < 4; mt++) {
            const size_t r0 = (size_t)(bm + wm * 64 + mt * 16 + gid) * N;
            const size_t r1 = r0 + 8 * N;
            #pragma unroll
            for (int nt = 0; nt < 8; nt++) {
                const int col = bn + wn * 64 + nt * 8 + tig * 2;
                const float2 v0 = *reinterpret_cast<const float2*>(R + r0 + col);
                const float2 v1 = *reinterpret_cast<const float2*>(R + r1 + col);
                acc[mt][nt][0] = v0.x; acc[mt][nt][1] = v0.y;
                acc[mt][nt][2] = v1.x; acc[mt][nt][3] = v1.y;
            }
        }
    } else {
        #pragma unroll
        for (int mt = 0; mt < 4; mt++)
            #pragma unroll
            for (int nt = 0; nt < 8; nt++)
                #pragma unroll
                for (int t = 0; t < 4; t++) acc[mt][nt][t] = 0.f;
    }

    const int NC = K / KC2;

    auto load_stage = [&](int buf, int k0) {
        __half* st = sm + buf * STAGE_ELEMS;
        #pragma unroll
        for (int o = 0; o < 4; o++) {
            const int idx = tid + o * 128;       // 0..511
            const int row = idx >> 2, seg = idx & 3;
            const int soff = row * SPAD + seg * 8;
            cp16(st + soff,        A + (size_t)(bm + row) * K + k0 + seg * 8);
            cp16(st + SLAB + soff, Bf + (size_t)(bn + row) * K + k0 + seg * 8);
        }
    };

    const int a_row = wm * 64 + (lane & 15);
    const int a_col = (lane >> 4) << 3;
    const int b_row = wn * 64 + (lane & 7) + ((lane >> 4) << 3);
    const int b_col = ((lane >> 3) & 1) << 3;

    load_stage(0, 0);
    cp_commit();
    if (NC > 1) {
        load_stage(1, KC2);
        cp_commit();
    }

    int buf = 0;
    for (int c = 0; c < NC; c++) {
        if (c + 2 < NC) {
            load_stage((c + 2) % 3, (c + 2) * KC2);
            cp_commit();
            cp_wait2();
        } else if (c + 1 < NC) {
            cp_wait1();
        } else {
            cp_wait0();
        }
        __syncthreads();

        const uint32_t st = smb + buf * STAGE_ELEMS * 2;  // bytes
        const uint32_t sA = st;
        const uint32_t sB = st + SLAB * 2;

        #pragma unroll
        for (int kk = 0; kk < KC2 / 16; kk++) {
            uint32_t bh[8][2];
            #pragma unroll
            for (int p = 0; p < 4; p++) {
                const uint32_t boff = ((b_row + p * 16) * SPAD + kk * 16 + b_col) * 2;
                uint32_t t4[4];
                ldsm4(t4, sB + boff);
                bh[2 * p][0] = t4[0]; bh[2 * p][1] = t4[1];
                bh[2 * p + 1][0] = t4[2]; bh[2 * p + 1][1] = t4[3];
            }
            #pragma unroll
            for (int mt = 0; mt < 4; mt++) {
                const uint32_t aoff = ((a_row + mt * 16) * SPAD + kk * 16 + a_col) * 2;
                uint32_t ah[4];
                ldsm4(ah, sA + aoff);
                #pragma unroll
                for (int nt = 0; nt < 8; nt++)
                    mma16816(acc[mt][nt], ah, bh[nt][0], bh[nt][1]);
            }
        }
        __syncthreads();
        buf = (buf + 1) % 3;
    }

    // ---- epilogue ----
    if (EPI == 1) {
        #pragma unroll
        for (int mt = 0; mt < 4; mt++) {
            const size_t r0 = (size_t)(bm + wm * 64 + mt * 16 + gid) * N;
            const size_t r1 = r0 + 8 * N;
            #pragma unroll
            for (int nt = 0; nt < 8; nt++) {
                const int col = bn + wn * 64 + nt * 8 + tig * 2;
                *reinterpret_cast<float2*>(C + r0 + col) =
                    make_float2(acc[mt][nt][0], acc[mt][nt][1]);
                *reinterpret_cast<float2*>(C + r1 + col) =
                    make_float2(acc[mt][nt][2], acc[mt][nt][3]);
            }
        }
    } else if (EPI == 2) {
        #pragma unroll
        for (int mt = 0; mt < 4; mt++) {
            const size_t r0 = (size_t)(bm + wm * 64 + mt * 16 + gid) * N;
            const size_t r1 = r0 + 8 * N;
            #pragma unroll
            for (int nt = 0; nt < 8; nt++) {
                const int col = bn + wn * 64 + nt * 8 + tig * 2;
                *reinterpret_cast<__half2*>(&Ch[r0 + col]) =
                    __floats2half2_rn(gelu_exact(acc[mt][nt][0]), gelu_exact(acc[mt][nt][1]));
                *reinterpret_cast<__half2*>(&Ch[r1 + col]) =
                    __floats2half2_rn(gelu_exact(acc[mt][nt][2]), gelu_exact(acc[mt][nt][3]));
            }
        }
    } else {
        // EPI == 3: qkv split.
        const int region = bn >> 10;    // 0 = q, 1 = k, 2 = v
        if (region == 0) {
            #pragma unroll
            for (int mt = 0; mt < 4; mt++) {
                const size_t r0 = (size_t)(bm + wm * 64 + mt * 16 + gid) * EMB;
                const size_t r1 = r0 + 8 * EMB;
                #pragma unroll
                for (int nt = 0; nt < 8; nt++) {
                    const int col = bn + wn * 64 + nt * 8 + tig * 2;
                    *reinterpret_cast<__half2*>(&Ch[r0 + col]) =
                        __floats2half2_rn(acc[mt][nt][0], acc[mt][nt][1]);
                    *reinterpret_cast<__half2*>(&Ch[r1 + col]) =
                        __floats2half2_rn(acc[mt][nt][2], acc[mt][nt][3]);
                }
            }
        } else if (region == 1) {
            const int hd = ((bn - 1024) >> 6) + wn;
            #pragma unroll
            for (int mt = 0; mt < 4; mt++) {
                const int row = bm + wm * 64 + mt * 16 + gid;
                const size_t k0 = ((size_t)hd * SEQ + row) * HS;
                const size_t k1 = k0 + 8 * HS;
                #pragma unroll
                for (int nt = 0; nt < 8; nt++) {
                    const int cc = nt * 8 + tig * 2;
                    *reinterpret_cast<__half2*>(&Kh[k0 + cc]) =
                        __floats2half2_rn(acc[mt][nt][0], acc[mt][nt][1]);
                    *reinterpret_cast<__half2*>(&Kh[k1 + cc]) =
                        __floats2half2_rn(acc[mt][nt][2], acc[mt][nt][3]);
                }
            }
        } else {
            __half* vs = sm;   // 128 x VPAD fp16 (34.8 KB)
            #pragma unroll
            for (int mt = 0; mt < 4; mt++) {
                const int lr0 = wm * 64 + mt * 16 + gid;
                #pragma unroll
                for (int nt = 0; nt < 8; nt++) {
                    const int lc = wn * 64 + nt * 8 + tig * 2;
                    *reinterpret_cast<__half2*>(&vs[lr0 * VPAD + lc]) =
                        __floats2half2_rn(acc[mt][nt][0], acc[mt][nt][1]);
                    *reinterpret_cast<__half2*>(&vs[(lr0 + 8) * VPAD + lc]) =
                        __floats2half2_rn(acc[mt][nt][2], acc[mt][nt][3]);
                }
            }
            __syncthreads();
            const int hdb = (bn - 2048) >> 6;
            #pragma unroll
            for (int i = 0; i < 64; i++) {
                const int idx = tid + i * 128;   // 0..8191
                const int d = idx >> 6;          // 0..127
                const int rp = idx & 63;         // row pair
                const __half2 v2 = __halves2half2(vs[(2 * rp) * VPAD + d],
                                                  vs[(2 * rp + 1) * VPAD + d]);
                const int hd = hdb + (d >> 6), dd = d & 63;
                *reinterpret_cast<__half2*>(
                    &Vt[((size_t)hd * HS + dd) * SEQ + bm + 2 * rp]) = v2;
            }
        }
    }
}

// ---------------- FA2 flash attention: 128-row q tiles, 8 warps ----------------
#define KVPAD 72
#define KVTILE (64 * KVPAD)
#define QTILE (128 * KVPAD)

__global__ __launch_bounds__(256) void flash2(
    const __half* __restrict__ qh,
    const __half* __restrict__ kh, const __half* __restrict__ vt,
    __half* __restrict__ outp) {
    extern __shared__ char smraw[];
    __half* Qs = reinterpret_cast<__half*>(smraw);   // 128 x 72
    __half* KB = Qs + QTILE;                         // [2 buf][Kh,Vt][64 x 72]

    const int tid = threadIdx.x;
    const int warp = tid >> 5, lane = tid & 31;
    const int gid = lane >> 2, tig = lane & 3;
    const int qb = (int)gridDim.x - 1 - (int)blockIdx.x;   // heavy tiles first
    const int qm = qb * 128;
    const int hd = blockIdx.y;

    {
        const __half2 sc = __floats2half2_rn(0.125f, 0.125f);  // exact (power of 2)
        for (int i = tid; i < 4096; i += 256) {
            const int r = i >> 5, c2 = (i & 31) * 2;
            const __half2 q2 = *reinterpret_cast<const __half2*>(
                qh + (size_t)(qm + r) * EMB + hd * HS + c2);
            *reinterpret_cast<__half2*>(&Qs[r * KVPAD + c2]) = __hmul2(q2, sc);
        }
    }
    __syncthreads();

    uint32_t qa[4][4];
    const int row0 = warp * 16 + gid;
    #pragma unroll
    for (int kk = 0; kk < 4; kk++) {
        qa[kk][0] = *reinterpret_cast<const uint32_t*>(&Qs[row0 * KVPAD + kk * 16 + tig * 2]);
        qa[kk][1] = *reinterpret_cast<const uint32_t*>(&Qs[(row0 + 8) * KVPAD + kk * 16 + tig * 2]);
        qa[kk][2] = *reinterpret_cast<const uint32_t*>(&Qs[row0 * KVPAD + kk * 16 + 8 + tig * 2]);
        qa[kk][3] = *reinterpret_cast<const uint32_t*>(&Qs[(row0 + 8) * KVPAD + kk * 16 + 8 + tig * 2]);
    }

    float o[8][4];
    #pragma unroll
    for (int j = 0; j < 8; j++)
        #pragma unroll
        for (int t = 0; t < 4; t++) o[j][t] = 0.f;
    float m0 = -1e30f, m1 = -1e30f, l0 = 0.f, l1 = 0.f;

    const size_t khb = (size_t)hd * SEQ * HS;
    const size_t vtb = (size_t)hd * HS * SEQ;
    const int NKT = 2 * qb + 2;

    auto prefetch = [&](int bufi, int kt) {
        __half* st = KB + bufi * (2 * KVTILE);
        #pragma unroll
        for (int o2 = 0; o2 < 2; o2++) {
            const int idx = tid + o2 * 256;   // 0..511
            const int r = idx >> 3, seg = idx & 7;
            const int so = r * KVPAD + seg * 8;
            cp16(st + so,          kh + khb + (size_t)(kt * 64 + r) * HS + seg * 8);
            cp16(st + KVTILE + so, vt + vtb + (size_t)r * SEQ + kt * 64 + seg * 8);
        }
    };

    prefetch(0, 0);
    cp_commit();

    for (int kt = 0; kt < NKT; kt++) {
        if (kt + 1 < NKT) {
            prefetch((kt + 1) & 1, kt + 1);
            cp_commit();
            cp_wait1();
        } else {
            cp_wait0();
        }
        __syncthreads();

        __half* st = KB + (kt & 1) * (2 * KVTILE);
        const __half* Kh = st;
        const __half* Vt = st + KVTILE;

        float s[8][4];
        #pragma unroll
        for (int j = 0; j < 8; j++)
            #pragma unroll
            for (int t = 0; t < 4; t++) s[j][t] = 0.f;
        #pragma unroll
        for (int kk = 0; kk < 4; kk++)
            #pragma unroll
            for (int j = 0; j < 8; j++) {
                const int off = (j * 8 + gid) * KVPAD + kk * 16 + tig * 2;
                const uint32_t b0 = *reinterpret_cast<const uint32_t*>(&Kh[off]);
                const uint32_t b1 = *reinterpret_cast<const uint32_t*>(&Kh[off + 8]);
                mma16816(s[j], qa[kk], b0, b1);
            }

        if (kt * 64 + 63 > qm + warp * 16) {
            const int rg0 = qm + row0;
            const int rg1 = rg0 + 8;
            #pragma unroll
            for (int j = 0; j < 8; j++) {
                const int c0 = kt * 64 + j * 8 + tig * 2;
                if (c0 > rg0)         s[j][0] = -1e30f;
                if (c0 + 1 > rg0)     s[j][1] = -1e30f;
                if (c0 > rg1)         s[j][2] = -1e30f;
                if (c0 + 1 > rg1)     s[j][3] = -1e30f;
            }
        }

        float mx0 = -1e30f, mx1 = -1e30f;
        #pragma unroll
        for (int j = 0; j < 8; j++) {
            mx0 = fmaxf(mx0, fmaxf(s[j][0], s[j][1]));
            mx1 = fmaxf(mx1, fmaxf(s[j][2], s[j][3]));
        }
        mx0 = fmaxf(mx0, __shfl_xor_sync(0xffffffffu, mx0, 1));
        mx0 = fmaxf(mx0, __shfl_xor_sync(0xffffffffu, mx0, 2));
        mx1 = fmaxf(mx1, __shfl_xor_sync(0xffffffffu, mx1, 1));
        mx1 = fmaxf(mx1, __shfl_xor_sync(0xffffffffu, mx1, 2));
        const float mn0 = fmaxf(m0, mx0), mn1 = fmaxf(m1, mx1);
        const float al0 = __expf(m0 - mn0), al1 = __expf(m1 - mn1);
        float rs0 = 0.f, rs1 = 0.f;
        #pragma unroll
        for (int j = 0; j < 8; j++) {
            s[j][0] = __expf(s[j][0] - mn0);
            s[j][1] = __expf(s[j][1] - mn0);
            s[j][2] = __expf(s[j][2] - mn1);
            s[j][3] = __expf(s[j][3] - mn1);
            rs0 += s[j][0] + s[j][1];
            rs1 += s[j][2] + s[j][3];
        }
        rs0 += __shfl_xor_sync(0xffffffffu, rs0, 1);
        rs0 += __shfl_xor_sync(0xffffffffu, rs0, 2);
        rs1 += __shfl_xor_sync(0xffffffffu, rs1, 1);
        rs1 += __shfl_xor_sync(0xffffffffu, rs1, 2);
        l0 = l0 * al0 + rs0;
        l1 = l1 * al1 + rs1;
        m0 = mn0;
        m1 = mn1;
        #pragma unroll
        for (int j = 0; j < 8; j++) {
            o[j][0] *= al0; o[j][1] *= al0;
            o[j][2] *= al1; o[j][3] *= al1;
        }

        #pragma unroll
        for (int kk = 0; kk < 4; kk++) {
            uint32_t pa[4];
            pa[0] = pack_h2(s[2 * kk][0], s[2 * kk][1]);
            pa[1] = pack_h2(s[2 * kk][2], s[2 * kk][3]);
            pa[2] = pack_h2(s[2 * kk + 1][0], s[2 * kk + 1][1]);
            pa[3] = pack_h2(s[2 * kk + 1][2], s[2 * kk + 1][3]);
            #pragma unroll
            for (int j = 0; j < 8; j++) {
                const int off = (j * 8 + gid) * KVPAD + kk * 16 + tig * 2;
                const uint32_t b0 = *reinterpret_cast<const uint32_t*>(&Vt[off]);
                const uint32_t b1 = *reinterpret_cast<const uint32_t*>(&Vt[off + 8]);
                mma16816(o[j], pa, b0, b1);
            }
        }
        __syncthreads();
    }

    const float inv0 = 1.0f / l0, inv1 = 1.0f / l1;
    #pragma unroll
    for (int j = 0; j < 8; j++) {
        const int d = hd * HS + j * 8 + tig * 2;
        const size_t r0o = (size_t)(qm + row0) * EMB + d;
        const size_t r1o = (size_t)(qm + row0 + 8) * EMB + d;
        *reinterpret_cast<__half2*>(&outp[r0o]) =
            __floats2half2_rn(o[j][0] * inv0, o[j][1] * inv0);
        *reinterpret_cast<__half2*>(&outp[r1o]) =
            __floats2half2_rn(o[j][2] * inv1, o[j][3] * inv1);
    }
}

// ---------------- launch ----------------
extern "C" void kernel_launch(void* const* d_in, const int* in_sizes, int n_in,
                              void* d_out, int out_size) {
    const float* x           = (const float*)d_in[0];
    const float* w_qkv       = (const float*)d_in[1];
    const float* w_attn_proj = (const float*)d_in[2];
    const float* w_fc        = (const float*)d_in[3];
    const float* w_mlp_proj  = (const float*)d_in[4];
    const float* ln1_w       = (const float*)d_in[5];
    const float* ln2_w       = (const float*)d_in[6];
    float* out = (float*)d_out;

    __half *p_h, *p_attn, *p_fc, *p_qh, *p_kh, *p_vt;
    __half *p_wqkv, *p_wproj, *p_wfc, *p_wmlp;
    float *p_x1;
    cudaGetSymbolAddress((void**)&p_h, g_h);
    cudaGetSymbolAddress((void**)&p_qh, g_qh);
    cudaGetSymbolAddress((void**)&p_kh, g_kh);
    cudaGetSymbolAddress((void**)&p_vt, g_vt);
    cudaGetSymbolAddress((void**)&p_attn, g_attn);
    cudaGetSymbolAddress((void**)&p_x1, g_x1);
    cudaGetSymbolAddress((void**)&p_fc, g_fc);
    cudaGetSymbolAddress((void**)&p_wqkv, g_wqkv);
    cudaGetSymbolAddress((void**)&p_wproj, g_wproj);
    cudaGetSymbolAddress((void**)&p_wfc, g_wfc);
    cudaGetSymbolAddress((void**)&p_wmlp, g_wmlp);

    const int gemm_smem = 3 * STAGE_ELEMS * (int)sizeof(__half);        // 61,440 B
    cudaFuncSetAttribute(mma_gemm<1>, cudaFuncAttributeMaxDynamicSharedMemorySize, gemm_smem);
    cudaFuncSetAttribute(mma_gemm<2>, cudaFuncAttributeMaxDynamicSharedMemorySize, gemm_smem);
    cudaFuncSetAttribute(mma_gemm<3>, cudaFuncAttributeMaxDynamicSharedMemorySize, gemm_smem);
    const int flash_smem = (QTILE + 4 * KVTILE) * (int)sizeof(__half);  // 55,296 B
    cudaFuncSetAttribute(flash2, cudaFuncAttributeMaxDynamicSharedMemorySize, flash_smem);

    // 0. h = LN(x, ln1)
    ln_kernel<<<SEQ, 256>>>(x, ln1_w, p_h);
    // 1-4. weight transpose to fp16 (64x64 tiles)
    wt_kernel<<<dim3(C3 / 64, EMB / 64), 256>>>(w_qkv, p_wqkv, EMB, C3);
    wt_kernel<<<dim3(EMB / 64, EMB / 64), 256>>>(w_attn_proj, p_wproj, EMB, EMB);
    wt_kernel<<<dim3(CFC / 64, EMB / 64), 256>>>(w_fc, p_wfc, EMB, CFC);
    wt_kernel<<<dim3(EMB / 64, CFC / 64), 256>>>(w_mlp_proj, p_wmlp, CFC, EMB);
    // 5. qkv = h @ w_qkv -> Q fp16 / K [hd][s][64] / V transposed (fused layouts)
    mma_gemm<3><<<dim3(C3 / 128, SEQ / 128), 128, gemm_smem>>>(
        p_h, p_wqkv, nullptr, nullptr, p_qh, p_kh, p_vt, SEQ, C3, EMB);
    // 6. attention (FA2, 128-row q tiles)
    flash2<<<dim3(SEQ / 128, NHEAD), 256, flash_smem>>>(p_qh, p_kh, p_vt, p_attn);
    // 7. x1 = x + attn @ w_attn_proj
    mma_gemm<1><<<dim3(EMB / 128, SEQ / 128), 128, gemm_smem>>>(
        p_attn, p_wproj, x, p_x1, nullptr, nullptr, nullptr, SEQ, EMB, EMB);
    // 8. h = LN(x1, ln2)
    ln_kernel<<<SEQ, 256>>>(p_x1, ln2_w, p_h);
    // 9. fc = gelu(h @ w_fc)
    mma_gemm<2><<<dim3(CFC / 128, SEQ / 128), 128, gemm_smem>>>(
        p_h, p_wfc, nullptr, nullptr, p_fc, nullptr, nullptr, SEQ, CFC, EMB);
    // 10. out = x1 + fc @ w_mlp_proj
    mma_gemm<1><<<dim3(EMB / 128, SEQ / 128), 128, gemm_smem>>>(
        p_fc, p_wmlp, p_x1, out, nullptr, nullptr, nullptr, SEQ, EMB, CFC);
}

// round 16
// speedup vs baseline: 1.0631x; 1.0138x over previous
#include <cuda_runtime.h>
#include <cuda_bf16.h>
#include <cuda_fp16.h>
#include <cstdint>
#include <math.h>

// Block: B=1, T=4096, C=1024, H=16, hs=64
#define SEQ 4096
#define EMB 1024
#define NHEAD 16
#define HS 64
#define C3 3072
#define CFC 4096

// ---------------- device scratch (no allocations allowed) ----------------
__device__ __half g_h[SEQ * EMB];          // LN out (fp16)
__device__ __half g_qh[SEQ * EMB];         // Q fp16 [seq][emb] (pre-scaled by 1/8)
__device__ __half g_kh[NHEAD * SEQ * HS];  // K fp16 [hd][seq][64]
__device__ __half g_vt[NHEAD * HS * SEQ];  // V fp16 transposed [hd][d][seq]
__device__ __half g_attn[SEQ * EMB];       // attention out (fp16)
__device__ float g_x1[SEQ * EMB];          // x + attn_proj
__device__ __half g_fc[SEQ * CFC];         // gelu(fc) (fp16)
// transposed fp16 weights: Wt[n][k]
__device__ __half g_wqkv[C3 * EMB];
__device__ __half g_wproj[EMB * EMB];
__device__ __half g_wfc[CFC * EMB];
__device__ __half g_wmlp[EMB * CFC];

__device__ __forceinline__ float gelu_exact(float v) {
    return 0.5f * v * (1.0f + erff(v * 0.70710678118654752440f));
}

// ---- smem/cp.async/mma helpers ----
__device__ __forceinline__ uint32_t smem_u32(const void* p) {
    uint32_t a;
    asm("{ .reg .u64 t; cvta.to.shared.u64 t, %1; cvt.u32.u64 %0, t; }" : "=r"(a) : "l"(p));
    return a;
}
__device__ __forceinline__ void cp16(void* sp, const void* gp) {
    asm volatile("cp.async.cg.shared.global [%0], [%1], 16;" :: "r"(smem_u32(sp)), "l"(gp));
}
__device__ __forceinline__ void cp_commit() {
    asm volatile("cp.async.commit_group;" ::: "memory");
}
__device__ __forceinline__ void cp_wait0() {
    asm volatile("cp.async.wait_group 0;" ::: "memory");
}
__device__ __forceinline__ void cp_wait1() {
    asm volatile("cp.async.wait_group 1;" ::: "memory");
}
__device__ __forceinline__ void cp_wait2() {
    asm volatile("cp.async.wait_group 2;" ::: "memory");
}
__device__ __forceinline__ void ldsm4(uint32_t* r, uint32_t addr) {
    asm volatile("ldmatrix.sync.aligned.m8n8.x4.shared.b16 {%0,%1,%2,%3}, [%4];"
                 : "=r"(r[0]), "=r"(r[1]), "=r"(r[2]), "=r"(r[3]) : "r"(addr));
}
__device__ __forceinline__ void mma16816(float* c, const uint32_t* a, uint32_t b0, uint32_t b1) {
    asm volatile(
        "mma.sync.aligned.m16n8k16.row.col.f32.f16.f16.f32 "
        "{%0,%1,%2,%3}, {%4,%5,%6,%7}, {%8,%9}, {%0,%1,%2,%3};"
        : "+f"(c[0]), "+f"(c[1]), "+f"(c[2]), "+f"(c[3])
        : "r"(a[0]), "r"(a[1]), "r"(a[2]), "r"(a[3]), "r"(b0), "r"(b1));
}
__device__ __forceinline__ uint32_t pack_h2(float x, float y) {
    __half2 h = __floats2half2_rn(x, y);
    return *reinterpret_cast<uint32_t*>(&h);
}

// ---------------- fused prologue: LN1 rows + all 4 weight transposes ----------------
// blocks [0, SEQ): LN of row b.  blocks [SEQ, SEQ+3072): 64x64 transpose tiles.
__global__ __launch_bounds__(256) void prep_kernel(
    const float* __restrict__ x, const float* __restrict__ ln1w, __half* __restrict__ hout,
    const float* __restrict__ w0, __half* __restrict__ t0,   // qkv : K=1024, N=3072 (768)
    const float* __restrict__ w1, __half* __restrict__ t1,   // proj: K=1024, N=1024 (256)
    const float* __restrict__ w2, __half* __restrict__ t2,   // fc  : K=1024, N=4096 (1024)
    const float* __restrict__ w3, __half* __restrict__ t3) { // mlp : K=4096, N=1024 (1024)
    __shared__ float tile[64][65];
    const int tid = threadIdx.x;
    int b = blockIdx.x;

    if (b < SEQ) {
        // ---- LayerNorm row b -> fp16 ----
        const float4 v = reinterpret_cast<const float4*>(x + (size_t)b * EMB)[tid];
        float s = v.x + v.y + v.z + v.w;
        float q = v.x * v.x + v.y * v.y + v.z * v.z + v.w * v.w;
        #pragma unroll
        for (int off = 16; off > 0; off >>= 1) {
            s += __shfl_xor_sync(0xffffffffu, s, off);
            q += __shfl_xor_sync(0xffffffffu, q, off);
        }
        float* ws = &tile[0][0];
        float* wq = &tile[0][8];
        float* stat = &tile[0][16];
        const int wid = tid >> 5, lane = tid & 31;
        if (lane == 0) { ws[wid] = s; wq[wid] = q; }
        __syncthreads();
        if (tid == 0) {
            float S = 0.f, Q = 0.f;
            #pragma unroll
            for (int i = 0; i < 8; i++) { S += ws[i]; Q += wq[i]; }
            float mean = S * (1.0f / EMB);
            float var = Q * (1.0f / EMB) - mean * mean;
            stat[0] = mean;
            stat[1] = rsqrtf(var + 1e-5f);
        }
        __syncthreads();
        const float mean = stat[0], rstd = stat[1];
        const float4 g = reinterpret_cast<const float4*>(ln1w)[tid];
        __half2 o0 = __floats2half2_rn((v.x - mean) * rstd * g.x, (v.y - mean) * rstd * g.y);
        __half2 o1 = __floats2half2_rn((v.z - mean) * rstd * g.z, (v.w - mean) * rstd * g.w);
        *reinterpret_cast<__half2*>(hout + (size_t)b * EMB + tid * 4) = o0;
        *reinterpret_cast<__half2*>(hout + (size_t)b * EMB + tid * 4 + 2) = o1;
        return;
    }

    // ---- weight transpose tile ----
    b -= SEQ;
    const float* W;
    __half* T;
    int K, N, bn, bk;
    if (b < 768)        { W = w0; T = t0; K = 1024; N = 3072; bn = (b % 48) * 64; bk = (b / 48) * 64; }
    else if (b < 1024)  { const int i = b - 768;  W = w1; T = t1; K = 1024; N = 1024; bn = (i % 16) * 64; bk = (i / 16) * 64; }
    else if (b < 2048)  { const int i = b - 1024; W = w2; T = t2; K = 1024; N = 4096; bn = (i % 64) * 64; bk = (i / 64) * 64; }
    else                { const int i = b - 2048; W = w3; T = t3; K = 4096; N = 1024; bn = (i % 16) * 64; bk = (i / 16) * 64; }

    const int r0 = tid >> 4;            // 0..15
    const int c4 = (tid & 15) * 4;      // 0..60
    #pragma unroll
    for (int rr = 0; rr < 4; rr++) {
        const int row = r0 + rr * 16;
        const float4 v = *reinterpret_cast<const float4*>(W + (size_t)(bk + row) * N + bn + c4);
        tile[row][c4 + 0] = v.x;
        tile[row][c4 + 1] = v.y;
        tile[row][c4 + 2] = v.z;
        tile[row][c4 + 3] = v.w;
    }
    __syncthreads();
    #pragma unroll
    for (int i = 0; i < 8; i++) {
        const int idx = tid + i * 256;       // 0..2047
        const int orow = idx >> 5;           // 0..63 (n)
        const int ocp = idx & 31;            // half2 pair (k/2)
        const __half2 h2 = __floats2half2_rn(tile[2 * ocp][orow], tile[2 * ocp + 1][orow]);
        *reinterpret_cast<__half2*>(&T[(size_t)(bn + orow) * K + bk + 2 * ocp]) = h2;
    }
}

// ---------------- LayerNorm -> fp16 (for LN2) ----------------
__global__ void ln_kernel(const float* __restrict__ x, const float* __restrict__ w,
                          __half* __restrict__ outp) {
    const int row = blockIdx.x;
    const int tid = threadIdx.x;
    const float4 v = reinterpret_cast<const float4*>(x + (size_t)row * EMB)[tid];

    float s = v.x + v.y + v.z + v.w;
    float q = v.x * v.x + v.y * v.y + v.z * v.z + v.w * v.w;
    #pragma unroll
    for (int off = 16; off > 0; off >>= 1) {
        s += __shfl_xor_sync(0xffffffffu, s, off);
        q += __shfl_xor_sync(0xffffffffu, q, off);
    }
    __shared__ float ws[8], wq[8], s_mean, s_rstd;
    const int wid = tid >> 5, lane = tid & 31;
    if (lane == 0) { ws[wid] = s; wq[wid] = q; }
    __syncthreads();
    if (tid == 0) {
        float S = 0.f, Q = 0.f;
        #pragma unroll
        for (int i = 0; i < 8; i++) { S += ws[i]; Q += wq[i]; }
        float mean = S * (1.0f / EMB);
        float var = Q * (1.0f / EMB) - mean * mean;
        s_mean = mean;
        s_rstd = rsqrtf(var + 1e-5f);
    }
    __syncthreads();
    const float mean = s_mean, rstd = s_rstd;
    const float4 g = reinterpret_cast<const float4*>(w)[tid];
    __half2 o0 = __floats2half2_rn((v.x - mean) * rstd * g.x, (v.y - mean) * rstd * g.y);
    __half2 o1 = __floats2half2_rn((v.z - mean) * rstd * g.z, (v.w - mean) * rstd * g.w);
    *reinterpret_cast<__half2*>(outp + (size_t)row * EMB + tid * 4) = o0;
    *reinterpret_cast<__half2*>(outp + (size_t)row * EMB + tid * 4 + 2) = o1;
}

// ---------------- raw-MMA GEMM: single-pass fp16, KC=32, 3-stage cp.async ----------------
// 128x128 CTA (4 warps, 64x64 warp tile).
// EPI: 1 = C = R + acc (fp32), 2 = gelu(acc)->fp16 Ch, 3 = qkv split (Q*0.125/K/Vt layouts)
#define KC2 32
#define SPAD 40                         // conflict-free ldmatrix (80B row stride)
#define SLAB (128 * SPAD)
#define STAGE_ELEMS (2 * SLAB)          // A, B
#define VPAD 136

template <int EPI>
__global__ __launch_bounds__(128, 2) void mma_gemm(
    const __half* __restrict__ A, const __half* __restrict__ Bf,
    const float* __restrict__ R, float* __restrict__ C,
    __half* __restrict__ Ch, __half* __restrict__ Kh, __half* __restrict__ Vt,
    int M, int N, int K) {
    extern __shared__ char smraw[];
    __half* sm = reinterpret_cast<__half*>(smraw);
    const uint32_t smb = smem_u32(sm);

    const int tid = threadIdx.x;
    const int warp = tid >> 5, lane = tid & 31;
    const int wm = warp & 1;        // 2 warps in M (64 rows)
    const int wn = warp >> 1;       // 2 warps in N (64 cols)
    const int gid = lane >> 2, tig = lane & 3;
    const int bm = blockIdx.y * 128, bn = blockIdx.x * 128;

    float acc[4][8][4];
    if (EPI == 1) {
        #pragma unroll
        for (int mt = 0; mt < 4; mt++) {
            const size_t r0 = (size_t)(bm + wm * 64 + mt * 16 + gid) * N;
            const size_t r1 = r0 + 8 * N;
            #pragma unroll
            for (int nt = 0; nt < 8; nt++) {
                const int col = bn + wn * 64 + nt * 8 + tig * 2;
                const float2 v0 = *reinterpret_cast<const float2*>(R + r0 + col);
                const float2 v1 = *reinterpret_cast<const float2*>(R + r1 + col);
                acc[mt][nt][0] = v0.x; acc[mt][nt][1] = v0.y;
                acc[mt][nt][2] = v1.x; acc[mt][nt][3] = v1.y;
            }
        }
    } else {
        #pragma unroll
        for (int mt = 0; mt < 4; mt++)
            #pragma unroll
            for (int nt = 0; nt < 8; nt++)
                #pragma unroll
                for (int t = 0; t < 4; t++) acc[mt][nt][t] = 0.f;
    }

    const int NC = K / KC2;

    auto load_stage = [&](int buf, int k0) {
        __half* st = sm + buf * STAGE_ELEMS;
        #pragma unroll
        for (int o = 0; o < 4; o++) {
            const int idx = tid + o * 128;       // 0..511
            const int row = idx >> 2, seg = idx & 3;
            const int soff = row * SPAD + seg * 8;
            cp16(st + soff,        A + (size_t)(bm + row) * K + k0 + seg * 8);
            cp16(st + SLAB + soff, Bf + (size_t)(bn + row) * K + k0 + seg * 8);
        }
    };

    const int a_row = wm * 64 + (lane & 15);
    const int a_col = (lane >> 4) << 3;
    const int b_row = wn * 64 + (lane & 7) + ((lane >> 4) << 3);
    const int b_col = ((lane >> 3) & 1) << 3;

    load_stage(0, 0);
    cp_commit();
    if (NC > 1) {
        load_stage(1, KC2);
        cp_commit();
    }

    int buf = 0;
    for (int c = 0; c < NC; c++) {
        if (c + 2 < NC) {
            load_stage((c + 2) % 3, (c + 2) * KC2);
            cp_commit();
            cp_wait2();
        } else if (c + 1 < NC) {
            cp_wait1();
        } else {
            cp_wait0();
        }
        __syncthreads();

        const uint32_t st = smb + buf * STAGE_ELEMS * 2;  // bytes
        const uint32_t sA = st;
        const uint32_t sB = st + SLAB * 2;

        #pragma unroll
        for (int kk = 0; kk < KC2 / 16; kk++) {
            uint32_t bh[8][2];
            #pragma unroll
            for (int p = 0; p < 4; p++) {
                const uint32_t boff = ((b_row + p * 16) * SPAD + kk * 16 + b_col) * 2;
                uint32_t t4[4];
                ldsm4(t4, sB + boff);
                bh[2 * p][0] = t4[0]; bh[2 * p][1] = t4[1];
                bh[2 * p + 1][0] = t4[2]; bh[2 * p + 1][1] = t4[3];
            }
            #pragma unroll
            for (int mt = 0; mt < 4; mt++) {
                const uint32_t aoff = ((a_row + mt * 16) * SPAD + kk * 16 + a_col) * 2;
                uint32_t ah[4];
                ldsm4(ah, sA + aoff);
                #pragma unroll
                for (int nt = 0; nt < 8; nt++)
                    mma16816(acc[mt][nt], ah, bh[nt][0], bh[nt][1]);
            }
        }
        __syncthreads();
        buf = (buf + 1) % 3;
    }

    // ---- epilogue ----
    if (EPI == 1) {
        #pragma unroll
        for (int mt = 0; mt < 4; mt++) {
            const size_t r0 = (size_t)(bm + wm * 64 + mt * 16 + gid) * N;
            const size_t r1 = r0 + 8 * N;
            #pragma unroll
            for (int nt = 0; nt < 8; nt++) {
                const int col = bn + wn * 64 + nt * 8 + tig * 2;
                *reinterpret_cast<float2*>(C + r0 + col) =
                    make_float2(acc[mt][nt][0], acc[mt][nt][1]);
                *reinterpret_cast<float2*>(C + r1 + col) =
                    make_float2(acc[mt][nt][2], acc[mt][nt][3]);
            }
        }
    } else if (EPI == 2) {
        #pragma unroll
        for (int mt = 0; mt < 4; mt++) {
            const size_t r0 = (size_t)(bm + wm * 64 + mt * 16 + gid) * N;
            const size_t r1 = r0 + 8 * N;
            #pragma unroll
            for (int nt = 0; nt < 8; nt++) {
                const int col = bn + wn * 64 + nt * 8 + tig * 2;
                *reinterpret_cast<__half2*>(&Ch[r0 + col]) =
                    __floats2half2_rn(gelu_exact(acc[mt][nt][0]), gelu_exact(acc[mt][nt][1]));
                *reinterpret_cast<__half2*>(&Ch[r1 + col]) =
                    __floats2half2_rn(gelu_exact(acc[mt][nt][2]), gelu_exact(acc[mt][nt][3]));
            }
        }
    } else {
        // EPI == 3: qkv split.
        const int region = bn >> 10;    // 0 = q, 1 = k, 2 = v
        if (region == 0) {
            // Q fp16 [seq][emb], pre-scaled by 1/8 (exact power of two)
            #pragma unroll
            for (int mt = 0; mt < 4; mt++) {
                const size_t r0 = (size_t)(bm + wm * 64 + mt * 16 + gid) * EMB;
                const size_t r1 = r0 + 8 * EMB;
                #pragma unroll
                for (int nt = 0; nt < 8; nt++) {
                    const int col = bn + wn * 64 + nt * 8 + tig * 2;
                    *reinterpret_cast<__half2*>(&Ch[r0 + col]) =
                        __floats2half2_rn(acc[mt][nt][0] * 0.125f, acc[mt][nt][1] * 0.125f);
                    *reinterpret_cast<__half2*>(&Ch[r1 + col]) =
                        __floats2half2_rn(acc[mt][nt][2] * 0.125f, acc[mt][nt][3] * 0.125f);
                }
            }
        } else if (region == 1) {
            const int hd = ((bn - 1024) >> 6) + wn;
            #pragma unroll
            for (int mt = 0; mt < 4; mt++) {
                const int row = bm + wm * 64 + mt * 16 + gid;
                const size_t k0 = ((size_t)hd * SEQ + row) * HS;
                const size_t k1 = k0 + 8 * HS;
                #pragma unroll
                for (int nt = 0; nt < 8; nt++) {
                    const int cc = nt * 8 + tig * 2;
                    *reinterpret_cast<__half2*>(&Kh[k0 + cc]) =
                        __floats2half2_rn(acc[mt][nt][0], acc[mt][nt][1]);
                    *reinterpret_cast<__half2*>(&Kh[k1 + cc]) =
                        __floats2half2_rn(acc[mt][nt][2], acc[mt][nt][3]);
                }
            }
        } else {
            __half* vs = sm;   // 128 x VPAD fp16 (34.8 KB)
            #pragma unroll
            for (int mt = 0; mt < 4; mt++) {
                const int lr0 = wm * 64 + mt * 16 + gid;
                #pragma unroll
                for (int nt = 0; nt < 8; nt++) {
                    const int lc = wn * 64 + nt * 8 + tig * 2;
                    *reinterpret_cast<__half2*>(&vs[lr0 * VPAD + lc]) =
                        __floats2half2_rn(acc[mt][nt][0], acc[mt][nt][1]);
                    *reinterpret_cast<__half2*>(&vs[(lr0 + 8) * VPAD + lc]) =
                        __floats2half2_rn(acc[mt][nt][2], acc[mt][nt][3]);
                }
            }
            __syncthreads();
            const int hdb = (bn - 2048) >> 6;
            #pragma unroll
            for (int i = 0; i < 64; i++) {
                const int idx = tid + i * 128;   // 0..8191
                const int d = idx >> 6;          // 0..127
                const int rp = idx & 63;         // row pair
                const __half2 v2 = __halves2half2(vs[(2 * rp) * VPAD + d],
                                                  vs[(2 * rp + 1) * VPAD + d]);
                const int hd = hdb + (d >> 6), dd = d & 63;
                *reinterpret_cast<__half2*>(
                    &Vt[((size_t)hd * HS + dd) * SEQ + bm + 2 * rp]) = v2;
            }
        }
    }
}

// ---------------- FA2 flash attention: 128-row q tiles, 8 warps ----------------
#define KVPAD 72
#define KVTILE (64 * KVPAD)
#define QTILE (128 * KVPAD)

__global__ __launch_bounds__(256) void flash2(
    const __half* __restrict__ qh,
    const __half* __restrict__ kh, const __half* __restrict__ vt,
    __half* __restrict__ outp) {
    extern __shared__ char smraw[];
    __half* Qs = reinterpret_cast<__half*>(smraw);   // 128 x 72
    __half* KB = Qs + QTILE;                         // [2 buf][Kh,Vt][64 x 72]

    const int tid = threadIdx.x;
    const int warp = tid >> 5, lane = tid & 31;
    const int gid = lane >> 2, tig = lane & 3;
    const int qb = (int)gridDim.x - 1 - (int)blockIdx.x;   // heavy tiles first
    const int qm = qb * 128;
    const int hd = blockIdx.y;

    for (int i = tid; i < 4096; i += 256) {
        const int r = i >> 5, c2 = (i & 31) * 2;
        *reinterpret_cast<__half2*>(&Qs[r * KVPAD + c2]) =
            *reinterpret_cast<const __half2*>(qh + (size_t)(qm + r) * EMB + hd * HS + c2);
    }
    __syncthreads();

    uint32_t qa[4][4];
    const int row0 = warp * 16 + gid;
    #pragma unroll
    for (int kk = 0; kk < 4; kk++) {
        qa[kk][0] = *reinterpret_cast<const uint32_t*>(&Qs[row0 * KVPAD + kk * 16 + tig * 2]);
        qa[kk][1] = *reinterpret_cast<const uint32_t*>(&Qs[(row0 + 8) * KVPAD + kk * 16 + tig * 2]);
        qa[kk][2] = *reinterpret_cast<const uint32_t*>(&Qs[row0 * KVPAD + kk * 16 + 8 + tig * 2]);
        qa[kk][3] = *reinterpret_cast<const uint32_t*>(&Qs[(row0 + 8) * KVPAD + kk * 16 + 8 + tig * 2]);
    }

    float o[8][4];
    #pragma unroll
    for (int j = 0; j < 8; j++)
        #pragma unroll
        for (int t = 0; t < 4; t++) o[j][t] = 0.f;
    float m0 = -1e30f, m1 = -1e30f, l0 = 0.f, l1 = 0.f;

    const size_t khb = (size_t)hd * SEQ * HS;
    const size_t vtb = (size_t)hd * HS * SEQ;
    const int NKT = 2 * qb + 2;

    auto prefetch = [&](int bufi, int kt) {
        __half* st = KB + bufi * (2 * KVTILE);
        #pragma unroll
        for (int o2 = 0; o2 < 2; o2++) {
            const int idx = tid + o2 * 256;   // 0..511
            const int r = idx >> 3, seg = idx & 7;
            const int so = r * KVPAD + seg * 8;
            cp16(st + so,          kh + khb + (size_t)(kt * 64 + r) * HS + seg * 8);
            cp16(st + KVTILE + so, vt + vtb + (size_t)r * SEQ + kt * 64 + seg * 8);
        }
    };

    prefetch(0, 0);
    cp_commit();

    for (int kt = 0; kt < NKT; kt++) {
        if (kt + 1 < NKT) {
            prefetch((kt + 1) & 1, kt + 1);
            cp_commit();
            cp_wait1();
        } else {
            cp_wait0();
        }
        __syncthreads();

        __half* st = KB + (kt & 1) * (2 * KVTILE);
        const __half* Kh = st;
        const __half* Vt = st + KVTILE;

        float s[8][4];
        #pragma unroll
        for (int j = 0; j < 8; j++)
            #pragma unroll
            for (int t = 0; t < 4; t++) s[j][t] = 0.f;
        #pragma unroll
        for (int kk = 0; kk < 4; kk++)
            #pragma unroll
            for (int j = 0; j < 8; j++) {
                const int off = (j * 8 + gid) * KVPAD + kk * 16 + tig * 2;
                const uint32_t b0 = *reinterpret_cast<const uint32_t*>(&Kh[off]);
                const uint32_t b1 = *reinterpret_cast<const uint32_t*>(&Kh[off + 8]);
                mma16816(s[j], qa[kk], b0, b1);
            }

        if (kt * 64 + 63 > qm + warp * 16) {
            const int rg0 = qm + row0;
            const int rg1 = rg0 + 8;
            #pragma unroll
            for (int j = 0; j < 8; j++) {
                const int c0 = kt * 64 + j * 8 + tig * 2;
                if (c0 > rg0)         s[j][0] = -1e30f;
                if (c0 + 1 > rg0)     s[j][1] = -1e30f;
                if (c0 > rg1)         s[j][2] = -1e30f;
                if (c0 + 1 > rg1)     s[j][3] = -1e30f;
            }
        }

        float mx0 = -1e30f, mx1 = -1e30f;
        #pragma unroll
        for (int j = 0; j < 8; j++) {
            mx0 = fmaxf(mx0, fmaxf(s[j][0], s[j][1]));
            mx1 = fmaxf(mx1, fmaxf(s[j][2], s[j][3]));
        }
        mx0 = fmaxf(mx0, __shfl_xor_sync(0xffffffffu, mx0, 1));
        mx0 = fmaxf(mx0, __shfl_xor_sync(0xffffffffu, mx0, 2));
        mx1 = fmaxf(mx1, __shfl_xor_sync(0xffffffffu, mx1, 1));
        mx1 = fmaxf(mx1, __shfl_xor_sync(0xffffffffu, mx1, 2));
        const float mn0 = fmaxf(m0, mx0), mn1 = fmaxf(m1, mx1);
        const float al0 = __expf(m0 - mn0), al1 = __expf(m1 - mn1);
        float rs0 = 0.f, rs1 = 0.f;
        #pragma unroll
        for (int j = 0; j < 8; j++) {
            s[j][0] = __expf(s[j][0] - mn0);
            s[j][1] = __expf(s[j][1] - mn0);
            s[j][2] = __expf(s[j][2] - mn1);
            s[j][3] = __expf(s[j][3] - mn1);
            rs0 += s[j][0] + s[j][1];
            rs1 += s[j][2] + s[j][3];
        }
        rs0 += __shfl_xor_sync(0xffffffffu, rs0, 1);
        rs0 += __shfl_xor_sync(0xffffffffu, rs0, 2);
        rs1 += __shfl_xor_sync(0xffffffffu, rs1, 1);
        rs1 += __shfl_xor_sync(0xffffffffu, rs1, 2);
        l0 = l0 * al0 + rs0;
        l1 = l1 * al1 + rs1;
        m0 = mn0;
        m1 = mn1;
        #pragma unroll
        for (int j = 0; j < 8; j++) {
            o[j][0] *= al0; o[j][1] *= al0;
            o[j][2] *= al1; o[j][3] *= al1;
        }

        #pragma unroll
        for (int kk = 0; kk < 4; kk++) {
            uint32_t pa[4];
            pa[0] = pack_h2(s[2 * kk][0], s[2 * kk][1]);
            pa[1] = pack_h2(s[2 * kk][2], s[2 * kk][3]);
            pa[2] = pack_h2(s[2 * kk + 1][0], s[2 * kk + 1][1]);
            pa[3] = pack_h2(s[2 * kk + 1][2], s[2 * kk + 1][3]);
            #pragma unroll
            for (int j = 0; j < 8; j++) {
                const int off = (j * 8 + gid) * KVPAD + kk * 16 + tig * 2;
                const uint32_t b0 = *reinterpret_cast<const uint32_t*>(&Vt[off]);
                const uint32_t b1 = *reinterpret_cast<const uint32_t*>(&Vt[off + 8]);
                mma16816(o[j], pa, b0, b1);
            }
        }
        __syncthreads();
    }

    const float inv0 = 1.0f / l0, inv1 = 1.0f / l1;
    #pragma unroll
    for (int j = 0; j < 8; j++) {
        const int d = hd * HS + j * 8 + tig * 2;
        const size_t r0o = (size_t)(qm + row0) * EMB + d;
        const size_t r1o = (size_t)(qm + row0 + 8) * EMB + d;
        *reinterpret_cast<__half2*>(&outp[r0o]) =
            __floats2half2_rn(o[j][0] * inv0, o[j][1] * inv0);
        *reinterpret_cast<__half2*>(&outp[r1o]) =
            __floats2half2_rn(o[j][2] * inv1, o[j][3] * inv1);
    }
}

// ---------------- launch ----------------
extern "C" void kernel_launch(void* const* d_in, const int* in_sizes, int n_in,
                              void* d_out, int out_size) {
    const float* x           = (const float*)d_in[0];
    const float* w_qkv       = (const float*)d_in[1];
    const float* w_attn_proj = (const float*)d_in[2];
    const float* w_fc        = (const float*)d_in[3];
    const float* w_mlp_proj  = (const float*)d_in[4];
    const float* ln1_w       = (const float*)d_in[5];
    const float* ln2_w       = (const float*)d_in[6];
    float* out = (float*)d_out;

    __half *p_h, *p_attn, *p_fc, *p_qh, *p_kh, *p_vt;
    __half *p_wqkv, *p_wproj, *p_wfc, *p_wmlp;
    float *p_x1;
    cudaGetSymbolAddress((void**)&p_h, g_h);
    cudaGetSymbolAddress((void**)&p_qh, g_qh);
    cudaGetSymbolAddress((void**)&p_kh, g_kh);
    cudaGetSymbolAddress((void**)&p_vt, g_vt);
    cudaGetSymbolAddress((void**)&p_attn, g_attn);
    cudaGetSymbolAddress((void**)&p_x1, g_x1);
    cudaGetSymbolAddress((void**)&p_fc, g_fc);
    cudaGetSymbolAddress((void**)&p_wqkv, g_wqkv);
    cudaGetSymbolAddress((void**)&p_wproj, g_wproj);
    cudaGetSymbolAddress((void**)&p_wfc, g_wfc);
    cudaGetSymbolAddress((void**)&p_wmlp, g_wmlp);

    const int gemm_smem = 3 * STAGE_ELEMS * (int)sizeof(__half);        // 61,440 B
    cudaFuncSetAttribute(mma_gemm<1>, cudaFuncAttributeMaxDynamicSharedMemorySize, gemm_smem);
    cudaFuncSetAttribute(mma_gemm<2>, cudaFuncAttributeMaxDynamicSharedMemorySize, gemm_smem);
    cudaFuncSetAttribute(mma_gemm<3>, cudaFuncAttributeMaxDynamicSharedMemorySize, gemm_smem);
    const int flash_smem = (QTILE + 4 * KVTILE) * (int)sizeof(__half);  // 55,296 B
    cudaFuncSetAttribute(flash2, cudaFuncAttributeMaxDynamicSharedMemorySize, flash_smem);

    // 0. fused prologue: LN1 (4096 blocks) + 4 weight transposes (3072 blocks)
    prep_kernel<<<SEQ + 3072, 256>>>(x, ln1_w, p_h,
                                     w_qkv, p_wqkv, w_attn_proj, p_wproj,
                                     w_fc, p_wfc, w_mlp_proj, p_wmlp);
    // 1. qkv = h @ w_qkv -> Q*0.125 fp16 / K [hd][s][64] / V transposed
    mma_gemm<3><<<dim3(C3 / 128, SEQ / 128), 128, gemm_smem>>>(
        p_h, p_wqkv, nullptr, nullptr, p_qh, p_kh, p_vt, SEQ, C3, EMB);
    // 2. attention (FA2, 128-row q tiles)
    flash2<<<dim3(SEQ / 128, NHEAD), 256, flash_smem>>>(p_qh, p_kh, p_vt, p_attn);
    // 3. x1 = x + attn @ w_attn_proj
    mma_gemm<1><<<dim3(EMB / 128, SEQ / 128), 128, gemm_smem>>>(
        p_attn, p_wproj, x, p_x1, nullptr, nullptr, nullptr, SEQ, EMB, EMB);
    // 4. h = LN(x1, ln2)
    ln_kernel<<<SEQ, 256>>>(p_x1, ln2_w, p_h);
    // 5. fc = gelu(h @ w_fc)
    mma_gemm<2><<<dim3(CFC / 128, SEQ / 128), 128, gemm_smem>>>(
        p_h, p_wfc, nullptr, nullptr, p_fc, nullptr, nullptr, SEQ, CFC, EMB);
    // 6. out = x1 + fc @ w_mlp_proj
    mma_gemm<1><<<dim3(EMB / 128, SEQ / 128), 128, gemm_smem>>>(
        p_fc, p_wmlp, p_x1, out, nullptr, nullptr, nullptr, SEQ, EMB, CFC);
}